// round 2
// baseline (speedup 1.0000x reference)
#include <cuda_runtime.h>
#include <cuda_bf16.h>

// PointPillarsScatter: out[b, c, y, x] = feat[p, c] where point p maps to (b, y, x),
// else 0. Duplicate pixels: highest point index wins (matches XLA scatter
// last-write-wins on duplicates).
//
// Strategy: output-major single write pass.
//   1) init pixel->point map to -1
//   2) atomicMax point ids into the map (deterministic duplicate resolution)
//   3) write the whole output once with float4 streaming stores, gathering
//      features only for hit pixels.

#define PP_NY 496
#define PP_NX 432
#define PP_C 64
#define PP_MAXB 8
#define PP_PLANE (PP_NY * PP_NX)   // 214272, divisible by 4

__device__ __align__(16) int g_pp_map[PP_MAXB * PP_PLANE];

__global__ void pp_init_map(int n4) {
    int t = blockIdx.x * blockDim.x + threadIdx.x;
    if (t < n4) {
        reinterpret_cast<int4*>(g_pp_map)[t] = make_int4(-1, -1, -1, -1);
    }
}

__global__ void pp_scatter_ids(const int* __restrict__ coords, int P) {
    int p = blockIdx.x * blockDim.x + threadIdx.x;
    if (p >= P) return;
    int b = coords[p * 4 + 0];
    int y = coords[p * 4 + 2];
    int x = coords[p * 4 + 3];
    atomicMax(&g_pp_map[b * PP_PLANE + y * PP_NX + x], p);
}

__global__ void pp_fill_out(const float* __restrict__ feat,
                            float* __restrict__ out, int total4) {
    int t = blockIdx.x * blockDim.x + threadIdx.x;
    if (t >= total4) return;
    int o  = t * 4;                 // first of 4 consecutive output elements
    int x  = o % PP_NX;             // x is a multiple of 4
    int r  = o / PP_NX;
    int y  = r % PP_NY;
    int r2 = r / PP_NY;
    int c  = r2 % PP_C;
    int b  = r2 / PP_C;

    int m = b * PP_PLANE + y * PP_NX + x;   // multiple of 4 -> int4 aligned
    const int4 ids = *reinterpret_cast<const int4*>(&g_pp_map[m]);

    float4 v;
    v.x = (ids.x < 0) ? 0.0f : __ldg(&feat[ids.x * PP_C + c]);
    v.y = (ids.y < 0) ? 0.0f : __ldg(&feat[ids.y * PP_C + c]);
    v.z = (ids.z < 0) ? 0.0f : __ldg(&feat[ids.z * PP_C + c]);
    v.w = (ids.w < 0) ? 0.0f : __ldg(&feat[ids.w * PP_C + c]);

    __stcs(reinterpret_cast<float4*>(out) + t, v);   // streaming: written once, never re-read
}

extern "C" void kernel_launch(void* const* d_in, const int* in_sizes, int n_in,
                              void* d_out, int out_size) {
    const float* feat   = (const float*)d_in[0];
    const int*   coords = (const int*)d_in[1];
    // d_in[2] = batch_size scalar; B derived from out_size instead.

    int P     = in_sizes[1] / 4;              // 48000
    int mapN  = out_size / PP_C;              // B * PLANE
    int mapN4 = mapN / 4;
    int tot4  = out_size / 4;

    pp_init_map<<<(mapN4 + 255) / 256, 256>>>(mapN4);
    pp_scatter_ids<<<(P + 255) / 256, 256>>>(coords, P);
    pp_fill_out<<<(tot4 + 255) / 256, 256>>>(feat, (float*)d_out, tot4);
}

// round 3
// speedup vs baseline: 1.0006x; 1.0006x over previous
#include <cuda_runtime.h>
#include <cuda_bf16.h>

// PointPillarsScatter: out[b, c, y, x] = feat[p, c] where point p maps to (b, y, x),
// else 0. Duplicate pixels: highest point index wins (matches XLA scatter
// last-write-wins on duplicates).
//
// Strategy: output-major single write pass.
//   1) init pixel->point map to -1
//   2) atomicMax point ids into the map (deterministic duplicate resolution)
//   3) write the whole output once with float4 streaming stores, gathering
//      features only for hit pixels.

#define PP_NY 496
#define PP_NX 432
#define PP_C 64
#define PP_MAXB 8
#define PP_PLANE (PP_NY * PP_NX)   // 214272, divisible by 4

__device__ __align__(16) int g_pp_map[PP_MAXB * PP_PLANE];

__global__ void pp_init_map(int n4) {
    int t = blockIdx.x * blockDim.x + threadIdx.x;
    if (t < n4) {
        reinterpret_cast<int4*>(g_pp_map)[t] = make_int4(-1, -1, -1, -1);
    }
}

__global__ void pp_scatter_ids(const int* __restrict__ coords, int P) {
    int p = blockIdx.x * blockDim.x + threadIdx.x;
    if (p >= P) return;
    int b = coords[p * 4 + 0];
    int y = coords[p * 4 + 2];
    int x = coords[p * 4 + 3];
    atomicMax(&g_pp_map[b * PP_PLANE + y * PP_NX + x], p);
}

__global__ void pp_fill_out(const float* __restrict__ feat,
                            float* __restrict__ out, int total4) {
    int t = blockIdx.x * blockDim.x + threadIdx.x;
    if (t >= total4) return;
    int o  = t * 4;                 // first of 4 consecutive output elements
    int x  = o % PP_NX;             // x is a multiple of 4
    int r  = o / PP_NX;
    int y  = r % PP_NY;
    int r2 = r / PP_NY;
    int c  = r2 % PP_C;
    int b  = r2 / PP_C;

    int m = b * PP_PLANE + y * PP_NX + x;   // multiple of 4 -> int4 aligned
    const int4 ids = *reinterpret_cast<const int4*>(&g_pp_map[m]);

    float4 v;
    v.x = (ids.x < 0) ? 0.0f : __ldg(&feat[ids.x * PP_C + c]);
    v.y = (ids.y < 0) ? 0.0f : __ldg(&feat[ids.y * PP_C + c]);
    v.z = (ids.z < 0) ? 0.0f : __ldg(&feat[ids.z * PP_C + c]);
    v.w = (ids.w < 0) ? 0.0f : __ldg(&feat[ids.w * PP_C + c]);

    __stcs(reinterpret_cast<float4*>(out) + t, v);   // streaming: written once, never re-read
}

extern "C" void kernel_launch(void* const* d_in, const int* in_sizes, int n_in,
                              void* d_out, int out_size) {
    const float* feat   = (const float*)d_in[0];
    const int*   coords = (const int*)d_in[1];
    // d_in[2] = batch_size scalar; B derived from out_size instead.

    int P     = in_sizes[1] / 4;              // 48000
    int mapN  = out_size / PP_C;              // B * PLANE
    int mapN4 = mapN / 4;
    int tot4  = out_size / 4;

    pp_init_map<<<(mapN4 + 255) / 256, 256>>>(mapN4);
    pp_scatter_ids<<<(P + 255) / 256, 256>>>(coords, P);
    pp_fill_out<<<(tot4 + 255) / 256, 256>>>(feat, (float*)d_out, tot4);
}